// round 3
// baseline (speedup 1.0000x reference)
#include <cuda_runtime.h>
#include <cuda_bf16.h>

// out[b,n] = sum_m x[b,n,m] * w1[m,0,n] + b1[0,n,0]
// x:  [256, 4096, 64] (m contiguous), w1: [64, 1, 4096] (n contiguous),
// b1: [4096], out: [256, 4096]
//
// Warp-cooperative: 16 lanes per (b,n) row; warp covers rows (n0,n0+1)
// -> every x LDG.128 is 512B fully-coalesced. w tile staged via smem
// (coalesced, kills the 16KB-stride gather). 8 loads in flight per warp.

#define N_DIM   4096
#define B_DIM   256
#define B_CHUNK 32
#define B_STRIDE_F4 (N_DIM * 16)        // float4 stride between batches
#define SW_PITCH 17                     // padded smem pitch

__global__ __launch_bounds__(256, 4) void superlinear_kernel(
    const float*  __restrict__ x,
    const float*  __restrict__ w,
    const float*  __restrict__ bias,
    float*        __restrict__ out)
{
    __shared__ float sw[64 * SW_PITCH]; // sw[m*17 + nn], nn = n - n0blk
    __shared__ float sb[16];

    const int tid  = threadIdx.x;
    const int warp = tid >> 5;
    const int lane = tid & 31;
    const int half = lane >> 4;          // which n of the warp's pair
    const int sub  = lane & 15;          // float4 slot within the row

    const int n0blk  = blockIdx.x * 16;
    const int n_pair = n0blk + warp * 2;
    const int n      = n_pair + half;
    const int b0     = blockIdx.y * B_CHUNK;

    // ---- stage w tile [64 m x 16 n] + bias, coalesced ----
    #pragma unroll
    for (int k = 0; k < 4; k++) {
        const int idx = tid + k * 256;          // 0..1023
        const int m   = idx >> 4;
        const int nn  = idx & 15;
        sw[m * SW_PITCH + nn] = w[m * N_DIM + n0blk + nn];
    }
    if (tid < 16) sb[tid] = bias[n0blk + tid];
    __syncthreads();

    // each lane's 4 weights: m = sub*4 .. sub*4+3, column (n - n0blk)
    const int nn = n - n0blk;
    const float w0 = sw[(sub * 4 + 0) * SW_PITCH + nn];
    const float w1v = sw[(sub * 4 + 1) * SW_PITCH + nn];
    const float w2 = sw[(sub * 4 + 2) * SW_PITCH + nn];
    const float w3 = sw[(sub * 4 + 3) * SW_PITCH + nn];
    const float bv = sb[nn];

    const float4* __restrict__ xr =
        (const float4*)(x + ((size_t)b0 * N_DIM + n) * 64) + sub;
    float* __restrict__ orow = out + (size_t)b0 * N_DIM + n_pair;

    #pragma unroll
    for (int i = 0; i < B_CHUNK; i += 8) {
        // 8 independent 512B loads in flight (16 KB apart).
        float4 a0 = xr[(size_t)(i + 0) * B_STRIDE_F4];
        float4 a1 = xr[(size_t)(i + 1) * B_STRIDE_F4];
        float4 a2 = xr[(size_t)(i + 2) * B_STRIDE_F4];
        float4 a3 = xr[(size_t)(i + 3) * B_STRIDE_F4];
        float4 a4 = xr[(size_t)(i + 4) * B_STRIDE_F4];
        float4 a5 = xr[(size_t)(i + 5) * B_STRIDE_F4];
        float4 a6 = xr[(size_t)(i + 6) * B_STRIDE_F4];
        float4 a7 = xr[(size_t)(i + 7) * B_STRIDE_F4];

        float p0 = a0.x * w0; p0 = fmaf(a0.y, w1v, p0); p0 = fmaf(a0.z, w2, p0); p0 = fmaf(a0.w, w3, p0);
        float p1 = a1.x * w0; p1 = fmaf(a1.y, w1v, p1); p1 = fmaf(a1.z, w2, p1); p1 = fmaf(a1.w, w3, p1);
        float p2 = a2.x * w0; p2 = fmaf(a2.y, w1v, p2); p2 = fmaf(a2.z, w2, p2); p2 = fmaf(a2.w, w3, p2);
        float p3 = a3.x * w0; p3 = fmaf(a3.y, w1v, p3); p3 = fmaf(a3.z, w2, p3); p3 = fmaf(a3.w, w3, p3);
        float p4 = a4.x * w0; p4 = fmaf(a4.y, w1v, p4); p4 = fmaf(a4.z, w2, p4); p4 = fmaf(a4.w, w3, p4);
        float p5 = a5.x * w0; p5 = fmaf(a5.y, w1v, p5); p5 = fmaf(a5.z, w2, p5); p5 = fmaf(a5.w, w3, p5);
        float p6 = a6.x * w0; p6 = fmaf(a6.y, w1v, p6); p6 = fmaf(a6.z, w2, p6); p6 = fmaf(a6.w, w3, p6);
        float p7 = a7.x * w0; p7 = fmaf(a7.y, w1v, p7); p7 = fmaf(a7.z, w2, p7); p7 = fmaf(a7.w, w3, p7);

        // Butterfly reduce within each 16-lane half.
        #pragma unroll
        for (int s = 8; s >= 1; s >>= 1) {
            p0 += __shfl_xor_sync(0xffffffffu, p0, s);
            p1 += __shfl_xor_sync(0xffffffffu, p1, s);
            p2 += __shfl_xor_sync(0xffffffffu, p2, s);
            p3 += __shfl_xor_sync(0xffffffffu, p3, s);
            p4 += __shfl_xor_sync(0xffffffffu, p4, s);
            p5 += __shfl_xor_sync(0xffffffffu, p5, s);
            p6 += __shfl_xor_sync(0xffffffffu, p6, s);
            p7 += __shfl_xor_sync(0xffffffffu, p7, s);
        }

        p0 += bv; p1 += bv; p2 += bv; p3 += bv;
        p4 += bv; p5 += bv; p6 += bv; p7 += bv;

        // lane 0 holds n_pair; pull n_pair+1 from lane 16; store float2.
        const float q0 = __shfl_sync(0xffffffffu, p0, 16);
        const float q1 = __shfl_sync(0xffffffffu, p1, 16);
        const float q2 = __shfl_sync(0xffffffffu, p2, 16);
        const float q3 = __shfl_sync(0xffffffffu, p3, 16);
        const float q4 = __shfl_sync(0xffffffffu, p4, 16);
        const float q5 = __shfl_sync(0xffffffffu, p5, 16);
        const float q6 = __shfl_sync(0xffffffffu, p6, 16);
        const float q7 = __shfl_sync(0xffffffffu, p7, 16);

        if (lane == 0) {
            *(float2*)(orow + (size_t)(i + 0) * N_DIM) = make_float2(p0, q0);
            *(float2*)(orow + (size_t)(i + 1) * N_DIM) = make_float2(p1, q1);
            *(float2*)(orow + (size_t)(i + 2) * N_DIM) = make_float2(p2, q2);
            *(float2*)(orow + (size_t)(i + 3) * N_DIM) = make_float2(p3, q3);
            *(float2*)(orow + (size_t)(i + 4) * N_DIM) = make_float2(p4, q4);
            *(float2*)(orow + (size_t)(i + 5) * N_DIM) = make_float2(p5, q5);
            *(float2*)(orow + (size_t)(i + 6) * N_DIM) = make_float2(p6, q6);
            *(float2*)(orow + (size_t)(i + 7) * N_DIM) = make_float2(p7, q7);
        }
    }
}

extern "C" void kernel_launch(void* const* d_in, const int* in_sizes, int n_in,
                              void* d_out, int out_size)
{
    const float* x    = (const float*)d_in[0];   // [256, 4096, 64]
    const float* w1   = (const float*)d_in[1];   // [64, 1, 4096]
    const float* b1   = (const float*)d_in[2];   // [1, 4096, 1]
    float*       out  = (float*)d_out;           // [256, 4096]

    dim3 block(256);                              // 8 warps -> 16 n per block
    dim3 grid(N_DIM / 16, B_DIM / B_CHUNK);       // (256, 8) = 2048 blocks
    superlinear_kernel<<<grid, block>>>(x, w1, b1, out);
}

// round 4
// speedup vs baseline: 1.0838x; 1.0838x over previous
#include <cuda_runtime.h>
#include <cuda_bf16.h>

// out[b,n] = sum_m x[b,n,m] * w1[m,0,n] + b1[0,n,0]
// x:  [256, 4096, 64] (m contiguous), w1: [64, 1, 4096] (n contiguous),
// b1: [4096], out: [256, 4096]
//
// Warp-cooperative: 16 lanes per (b,n) row; warp covers rows (n0,n0+1)
// -> every x LDG.128 is 512B fully-coalesced. w tile staged via smem
// (coalesced block load kills the 16KB-stride gather). 4 loads in
// flight per warp, ~36 regs -> high occupancy supplies the MLP.
// x loaded with .cs (streaming, no reuse), out stored with .cs.

#define N_DIM   4096
#define B_DIM   256
#define B_CHUNK 32
#define B_STRIDE_F4 (N_DIM * 16)        // float4 stride between batches
#define SW_PITCH 17                     // padded smem pitch

__global__ __launch_bounds__(256) void superlinear_kernel(
    const float*  __restrict__ x,
    const float*  __restrict__ w,
    const float*  __restrict__ bias,
    float*        __restrict__ out)
{
    __shared__ float sw[64 * SW_PITCH]; // sw[m*17 + nn]
    __shared__ float sb[16];

    const int tid  = threadIdx.x;
    const int warp = tid >> 5;
    const int lane = tid & 31;
    const int half = lane >> 4;          // which n of the warp's pair
    const int sub  = lane & 15;          // float4 slot within the row

    const int n0blk  = blockIdx.x * 16;
    const int n_pair = n0blk + warp * 2;
    const int n      = n_pair + half;
    const int b0     = blockIdx.y * B_CHUNK;

    // ---- stage w tile [64 m x 16 n] + bias, coalesced ----
    #pragma unroll
    for (int k = 0; k < 4; k++) {
        const int idx = tid + k * 256;          // 0..1023
        const int m   = idx >> 4;
        const int nn  = idx & 15;
        sw[m * SW_PITCH + nn] = __ldg(&w[m * N_DIM + n0blk + nn]);
    }
    if (tid < 16) sb[tid] = __ldg(&bias[n0blk + tid]);
    __syncthreads();

    const int nn = n - n0blk;
    const float w0 = sw[(sub * 4 + 0) * SW_PITCH + nn];
    const float w1v = sw[(sub * 4 + 1) * SW_PITCH + nn];
    const float w2 = sw[(sub * 4 + 2) * SW_PITCH + nn];
    const float w3 = sw[(sub * 4 + 3) * SW_PITCH + nn];
    const float bv = sb[nn];

    const float4* __restrict__ xr =
        (const float4*)(x + ((size_t)b0 * N_DIM + n) * 64) + sub;
    float* __restrict__ orow = out + (size_t)b0 * N_DIM + n_pair;

    #pragma unroll 2
    for (int i = 0; i < B_CHUNK; i += 4) {
        // 4 independent streaming 512B loads in flight (16 KB apart).
        const float4 a0 = __ldcs(&xr[(size_t)(i + 0) * B_STRIDE_F4]);
        const float4 a1 = __ldcs(&xr[(size_t)(i + 1) * B_STRIDE_F4]);
        const float4 a2 = __ldcs(&xr[(size_t)(i + 2) * B_STRIDE_F4]);
        const float4 a3 = __ldcs(&xr[(size_t)(i + 3) * B_STRIDE_F4]);

        float p0 = a0.x * w0; p0 = fmaf(a0.y, w1v, p0);
        p0 = fmaf(a0.z, w2, p0); p0 = fmaf(a0.w, w3, p0);
        float p1 = a1.x * w0; p1 = fmaf(a1.y, w1v, p1);
        p1 = fmaf(a1.z, w2, p1); p1 = fmaf(a1.w, w3, p1);
        float p2 = a2.x * w0; p2 = fmaf(a2.y, w1v, p2);
        p2 = fmaf(a2.z, w2, p2); p2 = fmaf(a2.w, w3, p2);
        float p3 = a3.x * w0; p3 = fmaf(a3.y, w1v, p3);
        p3 = fmaf(a3.z, w2, p3); p3 = fmaf(a3.w, w3, p3);

        // Butterfly reduce within each 16-lane half.
        #pragma unroll
        for (int s = 8; s >= 1; s >>= 1) {
            p0 += __shfl_xor_sync(0xffffffffu, p0, s);
            p1 += __shfl_xor_sync(0xffffffffu, p1, s);
            p2 += __shfl_xor_sync(0xffffffffu, p2, s);
            p3 += __shfl_xor_sync(0xffffffffu, p3, s);
        }

        p0 += bv; p1 += bv; p2 += bv; p3 += bv;

        // lane 0 holds n_pair; pull n_pair+1 from lane 16; store float2.
        const float q0 = __shfl_sync(0xffffffffu, p0, 16);
        const float q1 = __shfl_sync(0xffffffffu, p1, 16);
        const float q2 = __shfl_sync(0xffffffffu, p2, 16);
        const float q3 = __shfl_sync(0xffffffffu, p3, 16);

        if (lane == 0) {
            __stcs((float2*)(orow + (size_t)(i + 0) * N_DIM), make_float2(p0, q0));
            __stcs((float2*)(orow + (size_t)(i + 1) * N_DIM), make_float2(p1, q1));
            __stcs((float2*)(orow + (size_t)(i + 2) * N_DIM), make_float2(p2, q2));
            __stcs((float2*)(orow + (size_t)(i + 3) * N_DIM), make_float2(p3, q3));
        }
    }
}

extern "C" void kernel_launch(void* const* d_in, const int* in_sizes, int n_in,
                              void* d_out, int out_size)
{
    const float* x    = (const float*)d_in[0];   // [256, 4096, 64]
    const float* w1   = (const float*)d_in[1];   // [64, 1, 4096]
    const float* b1   = (const float*)d_in[2];   // [1, 4096, 1]
    float*       out  = (float*)d_out;           // [256, 4096]

    dim3 block(256);                              // 8 warps -> 16 n per block
    dim3 grid(N_DIM / 16, B_DIM / B_CHUNK);       // (256, 8) = 2048 blocks
    superlinear_kernel<<<grid, block>>>(x, w1, b1, out);
}

// round 6
// speedup vs baseline: 1.1353x; 1.0475x over previous
#include <cuda_runtime.h>
#include <cuda_bf16.h>

// out[b,n] = sum_m x[b,n,m] * w1[m,0,n] + b1[0,n,0]
// x:  [256, 4096, 64] (m contiguous), w1: [64, 1, 4096] (n contiguous),
// b1: [4096], out: [256, 4096]
//
// Warp-cooperative: 16 lanes per (b,n) row; warp covers rows (n0,n0+1)
// -> every x LDG.128 is 512B fully-coalesced (warp = 1KB contiguous).
// w tile staged via smem (coalesced block load). 4 loads in flight per
// warp @ 32 regs -> occupancy supplies the MLP. x loaded .cs, out .cs.
// B_CHUNK=16 -> 4096 blocks: 6.9 waves instead of 3.46 -> tail-wave
// imbalance smeared out.

#define N_DIM   4096
#define B_DIM   256
#define B_CHUNK 16
#define B_STRIDE_F4 (N_DIM * 16)        // float4 stride between batches
#define SW_PITCH 17                     // padded smem pitch

__global__ __launch_bounds__(256) void superlinear_kernel(
    const float*  __restrict__ x,
    const float*  __restrict__ w,
    const float*  __restrict__ bias,
    float*        __restrict__ out)
{
    __shared__ float sw[64 * SW_PITCH]; // sw[m*17 + nn]
    __shared__ float sb[16];

    const int tid  = threadIdx.x;
    const int warp = tid >> 5;
    const int lane = tid & 31;
    const int half = lane >> 4;          // which n of the warp's pair
    const int sub  = lane & 15;          // float4 slot within the row

    const int n0blk  = blockIdx.x * 16;
    const int n_pair = n0blk + warp * 2;
    const int n      = n_pair + half;
    const int b0     = blockIdx.y * B_CHUNK;

    // ---- stage w tile [64 m x 16 n] + bias, coalesced ----
    #pragma unroll
    for (int k = 0; k < 4; k++) {
        const int idx = tid + k * 256;          // 0..1023
        const int m   = idx >> 4;
        const int nn  = idx & 15;
        sw[m * SW_PITCH + nn] = __ldg(&w[m * N_DIM + n0blk + nn]);
    }
    if (tid < 16) sb[tid] = __ldg(&bias[n0blk + tid]);
    __syncthreads();

    const int nn = n - n0blk;
    const float w0 = sw[(sub * 4 + 0) * SW_PITCH + nn];
    const float w1v = sw[(sub * 4 + 1) * SW_PITCH + nn];
    const float w2 = sw[(sub * 4 + 2) * SW_PITCH + nn];
    const float w3 = sw[(sub * 4 + 3) * SW_PITCH + nn];
    const float bv = sb[nn];

    const float4* __restrict__ xr =
        (const float4*)(x + ((size_t)b0 * N_DIM + n) * 64) + sub;
    float* __restrict__ orow = out + (size_t)b0 * N_DIM + n_pair;

    #pragma unroll
    for (int i = 0; i < B_CHUNK; i += 4) {
        // 4 independent streaming 512B loads in flight (1 MB apart in b).
        const float4 a0 = __ldcs(&xr[(size_t)(i + 0) * B_STRIDE_F4]);
        const float4 a1 = __ldcs(&xr[(size_t)(i + 1) * B_STRIDE_F4]);
        const float4 a2 = __ldcs(&xr[(size_t)(i + 2) * B_STRIDE_F4]);
        const float4 a3 = __ldcs(&xr[(size_t)(i + 3) * B_STRIDE_F4]);

        float p0 = a0.x * w0; p0 = fmaf(a0.y, w1v, p0);
        p0 = fmaf(a0.z, w2, p0); p0 = fmaf(a0.w, w3, p0);
        float p1 = a1.x * w0; p1 = fmaf(a1.y, w1v, p1);
        p1 = fmaf(a1.z, w2, p1); p1 = fmaf(a1.w, w3, p1);
        float p2 = a2.x * w0; p2 = fmaf(a2.y, w1v, p2);
        p2 = fmaf(a2.z, w2, p2); p2 = fmaf(a2.w, w3, p2);
        float p3 = a3.x * w0; p3 = fmaf(a3.y, w1v, p3);
        p3 = fmaf(a3.z, w2, p3); p3 = fmaf(a3.w, w3, p3);

        // Butterfly reduce within each 16-lane half.
        #pragma unroll
        for (int s = 8; s >= 1; s >>= 1) {
            p0 += __shfl_xor_sync(0xffffffffu, p0, s);
            p1 += __shfl_xor_sync(0xffffffffu, p1, s);
            p2 += __shfl_xor_sync(0xffffffffu, p2, s);
            p3 += __shfl_xor_sync(0xffffffffu, p3, s);
        }

        p0 += bv; p1 += bv; p2 += bv; p3 += bv;

        // lane 0 holds n_pair; pull n_pair+1 from lane 16; store float2.
        const float q0 = __shfl_sync(0xffffffffu, p0, 16);
        const float q1 = __shfl_sync(0xffffffffu, p1, 16);
        const float q2 = __shfl_sync(0xffffffffu, p2, 16);
        const float q3 = __shfl_sync(0xffffffffu, p3, 16);

        if (lane == 0) {
            __stcs((float2*)(orow + (size_t)(i + 0) * N_DIM), make_float2(p0, q0));
            __stcs((float2*)(orow + (size_t)(i + 1) * N_DIM), make_float2(p1, q1));
            __stcs((float2*)(orow + (size_t)(i + 2) * N_DIM), make_float2(p2, q2));
            __stcs((float2*)(orow + (size_t)(i + 3) * N_DIM), make_float2(p3, q3));
        }
    }
}

extern "C" void kernel_launch(void* const* d_in, const int* in_sizes, int n_in,
                              void* d_out, int out_size)
{
    const float* x    = (const float*)d_in[0];   // [256, 4096, 64]
    const float* w1   = (const float*)d_in[1];   // [64, 1, 4096]
    const float* b1   = (const float*)d_in[2];   // [1, 4096, 1]
    float*       out  = (float*)d_out;           // [256, 4096]

    dim3 block(256);                              // 8 warps -> 16 n per block
    dim3 grid(N_DIM / 16, B_DIM / B_CHUNK);       // (256, 16) = 4096 blocks
    superlinear_kernel<<<grid, block>>>(x, w1, b1, out);
}